// round 15
// baseline (speedup 1.0000x reference)
#include <cuda_runtime.h>
#include <math.h>

#define T    128
#define D    64
#define H    256
#define HK   128
#define DD   (D*D)
#define ITERS 3
#define NB   128
#define NT   512
#define NSLOT 128
#define NBAR 16
#define NLEAF 16
#define SMEM_BYTES 147456   // 36864 floats: w2s 4096 | a3s 16384 | m3s 8192 | fys 8192

// ---- scratch (static device globals; no runtime allocation) ----
__device__ float A3_g[HK*T*T];         // 8 MB  A3[h][j][i] = w_ij * tanh(...)
__device__ float W2T_g[HK*DD];         // 2 MB  [h][e][d]
__device__ float bk2T_g[DD];           //       [e][d]
__device__ float fyP_g[2][T*D];        //       f(y) double-buffered by epoch parity
__device__ float cP_g[2][T*D];         //       bias projection, parity-buffered
__device__ float Gpart_g[NSLOT*T*D];   // 4 MB  slot = h
__device__ float G_g[T*D];

// epoch flags: single-writer, value = iteration+1; reset to 0 at kernel end
__device__ int flagF_g[T];
__device__ int flagG_g[HK];
__device__ int flagR_g[T];

// hierarchical grid barrier (replay-safe) — only 2 uses now
__device__ unsigned lfA[NBAR][NLEAF];
__device__ unsigned rtA[NBAR];
__device__ unsigned lfD[NBAR][NLEAF];
__device__ unsigned rtD[NBAR];

__device__ __forceinline__ void gsync(int b) {
    __syncthreads();
    if (threadIdx.x == 0) {
        __threadfence();
        int leaf = blockIdx.x & (NLEAF - 1);
        if (atomicAdd(&lfA[b][leaf], 1u) == 7u)
            atomicAdd(&rtA[b], 1u);
        while (*(volatile unsigned*)&rtA[b] < (unsigned)NLEAF) { }
        __threadfence();
        if (atomicAdd(&lfD[b][leaf], 1u) == 7u) {
            if (atomicAdd(&rtD[b], 1u) == (unsigned)(NLEAF - 1)) {
                #pragma unroll
                for (int l = 0; l < NLEAF; l++) { lfA[b][l] = 0u; lfD[b][l] = 0u; }
                rtA[b] = 0u;
                __threadfence();
                rtD[b] = 0u;
            }
        }
    }
    __syncthreads();
}

__device__ __forceinline__ void cpa16(float* s, const float* g) {
    unsigned sa = (unsigned)__cvta_generic_to_shared(s);
    asm volatile("cp.async.cg.shared.global [%0], [%1], 16;" :: "r"(sa), "l"(g));
}

// packed fp32x2 helpers (FFMA2 — only reachable via explicit PTX)
__device__ __forceinline__ unsigned long long splat2(float x) {
    unsigned long long r;
    unsigned int u = __float_as_uint(x);
    asm("mov.b64 %0, {%1, %1};" : "=l"(r) : "r"(u));
    return r;
}
__device__ __forceinline__ void ffma2(unsigned long long& d,
                                      unsigned long long a, unsigned long long b) {
    asm("fma.rn.f32x2 %0, %1, %2, %3;" : "=l"(d) : "l"(a), "l"(b), "l"(d));
}

// trapezoid weight w[i][j]: w = dt*(j<=i); w[i,i]*=0.5; w[:,0]*=0.5; w[0,:]=0
__device__ __forceinline__ float wfun(int i, int j, float dt) {
    if (i == 0 || j > i) return 0.0f;
    float v = dt;
    if (j == i) v *= 0.5f;
    if (j == 0) v *= 0.5f;
    return v;
}

__global__ void __launch_bounds__(NT, 1) mega(
    const float* __restrict__ z0, const float* __restrict__ t,
    const float* __restrict__ W1, const float* __restrict__ b1,
    const float* __restrict__ W2, const float* __restrict__ b2,
    const float* __restrict__ Wk1, const float* __restrict__ bk1,
    const float* __restrict__ Wk2, const float* __restrict__ bk2,
    float* __restrict__ out)
{
    extern __shared__ float sbuf[];
    float* w2s = sbuf;              // [e][d]   4096
    float* a3s = sbuf + 4096;       // [j][i]  16384
    float* m3s = sbuf + 20480;      // [j][d]   8192
    float* fys = sbuf + 28672;      // [j][e]   8192
    __shared__ float ts[T];
    __shared__ float yrow[D], hid[H], fyr[D];
    __shared__ float part8[8][D];
    __shared__ float hidpart[2][H];

    int bid = blockIdx.x, tid = threadIdx.x;

    // ================= SETUP =================
    {
        float* tr = a3s;            // 67*64 = 4288 floats scratch
        #pragma unroll
        for (int r = 0; r < 8; r++) {
            int idx = tid + r * 512;
            tr[(idx >> 6) * 67 + (idx & 63)] = Wk2[bid * DD + idx];
        }
        __syncthreads();
        #pragma unroll
        for (int r = 0; r < 8; r++) {
            int idx = tid + r * 512;
            W2T_g[bid * DD + idx] = tr[(idx & 63) * 67 + (idx >> 6)];
        }
        __syncthreads();
        if (bid == 0) {            // bk2T (block-uniform branch)
            #pragma unroll
            for (int r = 0; r < 8; r++) {
                int idx = tid + r * 512;
                tr[(idx >> 6) * 67 + (idx & 63)] = bk2[idx];
            }
            __syncthreads();
            #pragma unroll
            for (int r = 0; r < 8; r++) {
                int idx = tid + r * 512;
                bk2T_g[idx] = tr[(idx & 63) * 67 + (idx >> 6)];
            }
        }
    }
    if (tid < T) ts[tid] = t[tid];
    __syncthreads();
    float dt = ts[1] - ts[0];
    // A3[h=bid][j][i], coalesced over i
    {
        float wah = Wk1[bid], wbh = Wk1[HK + bid], bkh = bk1[bid];
        #pragma unroll 4
        for (int r = 0; r < 32; r++) {
            int idx = tid + r * 512;               // j = idx>>7, i = idx&127
            int j = idx >> 7, i = idx & 127;
            float v = tanhf(ts[i] * wah + ts[j] * wbh + bkh);
            A3_g[bid * (T * T) + idx] = wfun(i, j, dt) * v;
        }
    }

    gsync(0);

    // stage w2s + a3s ONCE (iteration-invariant per block), async
    {
        const float4* wg = (const float4*)&W2T_g[bid * DD];
        #pragma unroll
        for (int r = 0; r < 2; r++)
            cpa16(&w2s[(tid + r * 512) * 4], (const float*)(wg + tid + r * 512));
        const float4* ag = (const float4*)&A3_g[bid * (T * T)];
        #pragma unroll
        for (int r = 0; r < 8; r++)
            cpa16(&a3s[(tid + r * 512) * 4], (const float*)(ag + tid + r * 512));
        asm volatile("cp.async.commit_group;" ::: "memory");
    }

    // ================= FIXED-POINT ITERATIONS (flag-pipelined) =================
    for (int it = 0; it < ITERS; it++) {
        int ep = it + 1, par = it & 1;
        float* fyb = fyP_g[par];
        float* cb  = cP_g[par];

        // ---- phase F (block j): y_j from prev-epoch G, then fy[j], c[j] ----
        {
            int j = bid;
            int d = tid & 63, p = tid >> 6;        // 8-way split
            if (it == 0) {
                if (tid < D) yrow[tid] = z0[tid];
                __syncthreads();
            } else {
                if (tid < 128 && tid <= j)
                    while (((volatile int*)flagR_g)[tid] != it) { }
                __syncthreads();
                __threadfence();
                float s = 0.0f;
                #pragma unroll
                for (int r = 0; r < 16; r++) {     // rows i>j stale but zero-weighted
                    int i = p + r * 8;
                    s += wfun(j, i, dt) * __ldcg(&G_g[i * D + d]);
                }
                part8[p][d] = s;
                __syncthreads();
                if (p == 0) {
                    float acc = z0[d];
                    #pragma unroll
                    for (int r = 0; r < 8; r++) acc += part8[r][d];
                    yrow[d] = acc;
                }
                __syncthreads();
            }
            {
                int h = tid & 255, q = tid >> 8;   // 2-way split over e
                float s = (q == 0) ? b1[h] : 0.0f;
                #pragma unroll
                for (int ee = 0; ee < 32; ee++) {
                    int e = q * 32 + ee;
                    s += yrow[e] * W1[e * H + h];
                }
                hidpart[q][h] = s;
            }
            __syncthreads();
            if (tid < H)
                hid[tid] = tanhf(hidpart[0][tid] + hidpart[1][tid]);
            __syncthreads();
            {
                float s = 0.0f;
                #pragma unroll
                for (int hh = 0; hh < 32; hh++) {
                    int h = p * 32 + hh;
                    s += hid[h] * W2[h * D + d];
                }
                part8[p][d] = s;
            }
            __syncthreads();
            if (p == 0) {
                float f = b2[d];
                #pragma unroll
                for (int r = 0; r < 8; r++) f += part8[r][d];
                fyr[d] = f;
                fyb[j * D + d] = f;
            }
            __syncthreads();
            {
                float s = 0.0f;
                #pragma unroll
                for (int ee = 0; ee < 8; ee++) {
                    int e = p * 8 + ee;
                    s += bk2T_g[e * D + d] * fyr[e];
                }
                part8[p][d] = s;
            }
            __syncthreads();
            if (p == 0) {
                float cc = 0.0f;
                #pragma unroll
                for (int r = 0; r < 8; r++) cc += part8[r][d];
                cb[j * D + d] = cc;
            }
            __syncthreads();
            if (tid == 0) {
                __threadfence();
                ((volatile int*)flagF_g)[j] = ep;  // publish fy[j], c[j]
            }
        }

        // ---- phase MG (block h): wait all fy, m3 then G ----
        {
            int h = bid;
            if (tid < 128)
                while (((volatile int*)flagF_g)[tid] != ep) { }
            __syncthreads();
            __threadfence();
            {
                const float4* fg = (const float4*)fyb;
                float4* f4 = (float4*)fys;
                #pragma unroll
                for (int r = 0; r < 4; r++)
                    f4[tid + r * 512] = __ldcg(fg + tid + r * 512);
            }
            asm volatile("cp.async.wait_group 0;" ::: "memory");
            __syncthreads();
            // m3[j][d] = sum_e fys[j][e] * w2s[e][d]; thread: 4j x (2 d-pairs)
            {
                int dq = tid & 15, jt = tid >> 4;
                unsigned long long acc[4][2] = {};
                #pragma unroll
                for (int e4 = 0; e4 < 16; e4++) {
                    float4 fv[4];
                    #pragma unroll
                    for (int r = 0; r < 4; r++)
                        fv[r] = *(const float4*)&fys[(jt * 4 + r) * 64 + e4 * 4];
                    #pragma unroll
                    for (int ee = 0; ee < 4; ee++) {
                        int e = e4 * 4 + ee;
                        ulonglong2 w2 = *(const ulonglong2*)&w2s[e * 64 + dq * 4];
                        #pragma unroll
                        for (int r = 0; r < 4; r++) {
                            float f = (ee == 0) ? fv[r].x : (ee == 1) ? fv[r].y
                                    : (ee == 2) ? fv[r].z : fv[r].w;
                            unsigned long long fs = splat2(f);
                            ffma2(acc[r][0], fs, w2.x);
                            ffma2(acc[r][1], fs, w2.y);
                        }
                    }
                }
                #pragma unroll
                for (int r = 0; r < 4; r++)
                    *(ulonglong2*)&m3s[(jt * 4 + r) * 64 + dq * 4] =
                        make_ulonglong2(acc[r][0], acc[r][1]);
            }
            __syncthreads();
            // G[i][d] = sum_j a3s[j][i] * m3s[j][d]; thread: (2 i-pairs) x 4 d
            {
                int cx = tid & 15, cy = tid >> 4;
                int i0 = cy * 4;
                unsigned long long g2[2][4] = {};
                for (int jb = 0; jb < 8; jb++) {
                    if (jb * 16 <= i0 + 3) {   // chunk-level triangular skip
                        #pragma unroll
                        for (int jj = 0; jj < 16; jj++) {
                            int j = jb * 16 + jj;
                            ulonglong2 ap = *(const ulonglong2*)&a3s[j * 128 + i0];
                            float4 b = *(const float4*)&m3s[j * 64 + cx * 4];
                            unsigned long long bs0 = splat2(b.x), bs1 = splat2(b.y),
                                               bs2 = splat2(b.z), bs3 = splat2(b.w);
                            ffma2(g2[0][0], ap.x, bs0); ffma2(g2[0][1], ap.x, bs1);
                            ffma2(g2[0][2], ap.x, bs2); ffma2(g2[0][3], ap.x, bs3);
                            ffma2(g2[1][0], ap.y, bs0); ffma2(g2[1][1], ap.y, bs1);
                            ffma2(g2[1][2], ap.y, bs2); ffma2(g2[1][3], ap.y, bs3);
                        }
                    }
                }
                float* gp = &Gpart_g[h * (T * D)];
                #pragma unroll
                for (int ip = 0; ip < 2; ip++) {
                    float lo[4], hi[4];
                    #pragma unroll
                    for (int c = 0; c < 4; c++) {
                        unsigned int l, hb;
                        asm("mov.b64 {%0, %1}, %2;" : "=r"(l), "=r"(hb) : "l"(g2[ip][c]));
                        lo[c] = __uint_as_float(l);
                        hi[c] = __uint_as_float(hb);
                    }
                    *(float4*)&gp[(i0 + 2 * ip) * D + cx * 4] =
                        make_float4(lo[0], lo[1], lo[2], lo[3]);
                    *(float4*)&gp[(i0 + 2 * ip + 1) * D + cx * 4] =
                        make_float4(hi[0], hi[1], hi[2], hi[3]);
                }
            }
            __syncthreads();
            if (tid == 0) {
                __threadfence();
                ((volatile int*)flagG_g)[h] = ep;  // publish Gpart[h]
            }
        }

        // ---- phase R (block i): wait all Gpart, reduce + bias -> G[i] ----
        {
            int i = bid;
            if (tid < 128)
                while (((volatile int*)flagG_g)[tid] != ep) { }
            __syncthreads();
            __threadfence();
            int d = tid & 63, p = tid >> 6;        // 8-way
            float s = 0.0f;
            #pragma unroll
            for (int sl = p; sl < NSLOT; sl += 8)
                s += __ldcg(&Gpart_g[sl * (T * D) + i * D + d]);
            #pragma unroll
            for (int r = 0; r < 16; r++) {         // fixed trip; wfun zeroes jj>i
                int jj = p + r * 8;
                s += wfun(i, jj, dt) * __ldcg(&cb[jj * D + d]);
            }
            part8[p][d] = s;
            __syncthreads();
            if (p == 0) {
                float acc = 0.0f;
                #pragma unroll
                for (int r = 0; r < 8; r++) acc += part8[r][d];
                G_g[i * D + d] = acc;
            }
            __syncthreads();
            if (tid == 0) {
                __threadfence();
                ((volatile int*)flagR_g)[i] = ep;  // publish G[i]
            }
        }
    }

    // ---- tail: block 127 computes out = y0 + (w@G)_{127} ----
    if (bid == T - 1) {
        if (tid < 128)
            while (((volatile int*)flagR_g)[tid] != ITERS) { }
        __syncthreads();
        __threadfence();
        int d = tid & 63, p = tid >> 6;
        float s = 0.0f;
        #pragma unroll
        for (int r = 0; r < 16; r++) {
            int i = p + r * 8;
            s += wfun(T - 1, i, dt) * __ldcg(&G_g[i * D + d]);
        }
        part8[p][d] = s;
        __syncthreads();
        if (p == 0) {
            float acc = z0[d];
            #pragma unroll
            for (int r = 0; r < 8; r++) acc += part8[r][d];
            out[d] = acc;
        }
    }

    // final barrier, then each block resets its own flags (replay safety)
    gsync(1);
    if (tid == 0) {
        flagF_g[bid] = 0;
        flagG_g[bid] = 0;
        flagR_g[bid] = 0;
    }
}

extern "C" void kernel_launch(void* const* d_in, const int* in_sizes, int n_in,
                              void* d_out, int out_size) {
    const float* z0  = (const float*)d_in[0];
    const float* t   = (const float*)d_in[1];
    const float* W1  = (const float*)d_in[2];
    const float* b1  = (const float*)d_in[3];
    const float* W2  = (const float*)d_in[4];
    const float* b2  = (const float*)d_in[5];
    const float* Wk1 = (const float*)d_in[6];
    const float* bk1 = (const float*)d_in[7];
    const float* Wk2 = (const float*)d_in[8];
    const float* bk2 = (const float*)d_in[9];
    float* out = (float*)d_out;

    static int attr_done = 0;
    if (!attr_done) {
        cudaFuncSetAttribute(mega, cudaFuncAttributeMaxDynamicSharedMemorySize, SMEM_BYTES);
        attr_done = 1;
    }
    mega<<<NB, NT, SMEM_BYTES>>>(z0, t, W1, b1, W2, b2, Wk1, bk1, Wk2, bk2, out);
}

// round 16
// speedup vs baseline: 1.3286x; 1.3286x over previous
#include <cuda_runtime.h>
#include <math.h>

#define T    128
#define D    64
#define H    256
#define HK   128
#define DD   (D*D)
#define ITERS 3
#define NB   128
#define NT   512
#define NSLOT 128
#define NBAR 16
#define NLEAF 16
#define SMEM_BYTES 147456   // 36864 floats: w2s 4096 | a3s 16384 | m3s 8192 | fys 8192

// ---- scratch (static device globals; no runtime allocation) ----
// A3 and W2T are block-private -> live ONLY in smem now (no globals).
__device__ float bk2T_g[DD];           //       [e][d]
__device__ float fy_g[T*D];            //       f(y): [j][e]
__device__ float c_g[T*D];
__device__ float Gpart_g[T*NSLOT*D];   // 4 MB  [i][slot][d] (contiguous per-i for R)
__device__ float G_g[T*D];

// hierarchical grid barrier (replay-safe: last root-departer resets all)
__device__ unsigned lfA[NBAR][NLEAF];
__device__ unsigned rtA[NBAR];
__device__ unsigned lfD[NBAR][NLEAF];
__device__ unsigned rtD[NBAR];

__device__ __forceinline__ void gsync(int b) {
    __syncthreads();
    if (threadIdx.x == 0) {
        __threadfence();
        int leaf = blockIdx.x & (NLEAF - 1);
        if (atomicAdd(&lfA[b][leaf], 1u) == 7u)
            atomicAdd(&rtA[b], 1u);
        while (*(volatile unsigned*)&rtA[b] < (unsigned)NLEAF) { }
        __threadfence();
        if (atomicAdd(&lfD[b][leaf], 1u) == 7u) {
            if (atomicAdd(&rtD[b], 1u) == (unsigned)(NLEAF - 1)) {
                #pragma unroll
                for (int l = 0; l < NLEAF; l++) { lfA[b][l] = 0u; lfD[b][l] = 0u; }
                rtA[b] = 0u;
                __threadfence();
                rtD[b] = 0u;
            }
        }
    }
    __syncthreads();
}

// packed fp32x2 helpers (FFMA2 — only reachable via explicit PTX)
__device__ __forceinline__ unsigned long long splat2(float x) {
    unsigned long long r;
    unsigned int u = __float_as_uint(x);
    asm("mov.b64 %0, {%1, %1};" : "=l"(r) : "r"(u));
    return r;
}
__device__ __forceinline__ void ffma2(unsigned long long& d,
                                      unsigned long long a, unsigned long long b) {
    asm("fma.rn.f32x2 %0, %1, %2, %3;" : "=l"(d) : "l"(a), "l"(b), "l"(d));
}

// trapezoid weight w[i][j]: w = dt*(j<=i); w[i,i]*=0.5; w[:,0]*=0.5; w[0,:]=0
__device__ __forceinline__ float wfun(int i, int j, float dt) {
    if (i == 0 || j > i) return 0.0f;
    float v = dt;
    if (j == i) v *= 0.5f;
    if (j == 0) v *= 0.5f;
    return v;
}

__global__ void __launch_bounds__(NT, 1) mega(
    const float* __restrict__ z0, const float* __restrict__ t,
    const float* __restrict__ W1, const float* __restrict__ b1,
    const float* __restrict__ W2, const float* __restrict__ b2,
    const float* __restrict__ Wk1, const float* __restrict__ bk1,
    const float* __restrict__ Wk2, const float* __restrict__ bk2,
    float* __restrict__ out)
{
    extern __shared__ float sbuf[];
    float* w2s = sbuf;              // [e][d]   4096  (persistent all kernel)
    float* a3s = sbuf + 4096;       // [j][i]  16384  (persistent all kernel)
    float* m3s = sbuf + 20480;      // [j][d]   8192  (per-MG scratch)
    float* fys = sbuf + 28672;      // [j][e]   8192  (per-MG scratch)
    __shared__ float ts[T];
    __shared__ float yrow[D], hid[H], fyr[D];
    __shared__ float part8[8][D];
    __shared__ float hidpart[2][H];

    int bid = blockIdx.x, tid = threadIdx.x;

    // ================= SETUP =================
    // transpose Wk2[h=bid] DIRECTLY into persistent w2s ([e][d]) via padded scratch
    {
        float* tr = m3s;            // 67*64 = 4288 floats scratch (m3s region)
        #pragma unroll
        for (int r = 0; r < 8; r++) {
            int idx = tid + r * 512;               // d = idx>>6, e = idx&63
            tr[(idx >> 6) * 67 + (idx & 63)] = Wk2[bid * DD + idx];
        }
        __syncthreads();
        #pragma unroll
        for (int r = 0; r < 8; r++) {
            int idx = tid + r * 512;               // e = idx>>6, d = idx&63
            w2s[idx] = tr[(idx & 63) * 67 + (idx >> 6)];
        }
        __syncthreads();
        if (bid == 0) {            // bk2T (cross-block; block-uniform branch)
            #pragma unroll
            for (int r = 0; r < 8; r++) {
                int idx = tid + r * 512;
                tr[(idx >> 6) * 67 + (idx & 63)] = bk2[idx];
            }
            __syncthreads();
            #pragma unroll
            for (int r = 0; r < 8; r++) {
                int idx = tid + r * 512;
                bk2T_g[idx] = tr[(idx & 63) * 67 + (idx >> 6)];
            }
        }
    }
    if (tid < T) ts[tid] = t[tid];
    __syncthreads();
    float dt = ts[1] - ts[0];
    // A3[h=bid][j][i] DIRECTLY into persistent a3s (never leaves the block)
    {
        float wah = Wk1[bid], wbh = Wk1[HK + bid], bkh = bk1[bid];
        #pragma unroll 4
        for (int r = 0; r < 32; r++) {
            int idx = tid + r * 512;               // j = idx>>7, i = idx&127
            int j = idx >> 7, i = idx & 127;
            float v = tanhf(ts[i] * wah + ts[j] * wbh + bkh);
            a3s[idx] = wfun(i, j, dt) * v;
        }
    }

    int bar = 0;
    gsync(bar++);     // publishes bk2T before first F-phase use

    // ================= FIXED-POINT ITERATIONS =================
    for (int it = 0; it < ITERS; it++) {
        // ---- phase F (block j): y_j = y0 + (w@G)_j (fused), then fy[j], c[j] ----
        {
            int j = bid;
            int d = tid & 63, p = tid >> 6;        // 8-way split
            if (it == 0) {
                if (tid < D) yrow[tid] = z0[tid];
            } else {
                float s = 0.0f;
                #pragma unroll
                for (int r = 0; r < 16; r++) {     // fixed trip; wfun zeroes i>j
                    int i = p + r * 8;
                    s += wfun(j, i, dt) * __ldcg(&G_g[i * D + d]);
                }
                part8[p][d] = s;
                __syncthreads();
                if (p == 0) {
                    float acc = z0[d];
                    #pragma unroll
                    for (int r = 0; r < 8; r++) acc += part8[r][d];
                    yrow[d] = acc;
                }
            }
            __syncthreads();
            {
                int h = tid & 255, q = tid >> 8;   // 2-way split over e
                float s = (q == 0) ? b1[h] : 0.0f;
                #pragma unroll
                for (int ee = 0; ee < 32; ee++) {
                    int e = q * 32 + ee;
                    s += yrow[e] * W1[e * H + h];
                }
                hidpart[q][h] = s;
            }
            __syncthreads();
            if (tid < H)
                hid[tid] = tanhf(hidpart[0][tid] + hidpart[1][tid]);
            __syncthreads();
            {
                float s = 0.0f;
                #pragma unroll
                for (int hh = 0; hh < 32; hh++) {
                    int h = p * 32 + hh;
                    s += hid[h] * W2[h * D + d];
                }
                part8[p][d] = s;
            }
            __syncthreads();
            if (p == 0) {
                float f = b2[d];
                #pragma unroll
                for (int r = 0; r < 8; r++) f += part8[r][d];
                fyr[d] = f;
                fy_g[j * D + d] = f;               // row-major [j][e]
            }
            __syncthreads();
            {
                float s = 0.0f;
                #pragma unroll
                for (int ee = 0; ee < 8; ee++) {
                    int e = p * 8 + ee;
                    s += bk2T_g[e * D + d] * fyr[e];
                }
                part8[p][d] = s;
            }
            __syncthreads();
            if (p == 0) {
                float cc = 0.0f;
                #pragma unroll
                for (int r = 0; r < 8; r++) cc += part8[r][d];
                c_g[j * D + d] = cc;
            }
        }
        gsync(bar++);

        // ---- phase MG (block h): smem-resident tiles, f32x2 m3 then G ----
        {
            int h = bid;
            {
                const float4* fg = (const float4*)fy_g;
                float4* f4 = (float4*)fys;
                #pragma unroll
                for (int r = 0; r < 4; r++)
                    f4[tid + r * 512] = __ldcg(fg + tid + r * 512);
            }
            __syncthreads();
            // m3[j][d] = sum_e fys[j][e] * w2s[e][d]; thread: 4j x (2 d-pairs)
            {
                int dq = tid & 15, jt = tid >> 4;
                unsigned long long acc[4][2] = {};
                #pragma unroll
                for (int e4 = 0; e4 < 16; e4++) {
                    float4 fv[4];
                    #pragma unroll
                    for (int r = 0; r < 4; r++)
                        fv[r] = *(const float4*)&fys[(jt * 4 + r) * 64 + e4 * 4];
                    #pragma unroll
                    for (int ee = 0; ee < 4; ee++) {
                        int e = e4 * 4 + ee;
                        ulonglong2 w2 = *(const ulonglong2*)&w2s[e * 64 + dq * 4];
                        #pragma unroll
                        for (int r = 0; r < 4; r++) {
                            float f = (ee == 0) ? fv[r].x : (ee == 1) ? fv[r].y
                                    : (ee == 2) ? fv[r].z : fv[r].w;
                            unsigned long long fs = splat2(f);
                            ffma2(acc[r][0], fs, w2.x);
                            ffma2(acc[r][1], fs, w2.y);
                        }
                    }
                }
                #pragma unroll
                for (int r = 0; r < 4; r++)
                    *(ulonglong2*)&m3s[(jt * 4 + r) * 64 + dq * 4] =
                        make_ulonglong2(acc[r][0], acc[r][1]);
            }
            __syncthreads();
            // G[i][d] = sum_j a3s[j][i] * m3s[j][d]; thread: (2 i-pairs) x 4 d
            {
                int cx = tid & 15, cy = tid >> 4;
                int i0 = cy * 4;
                unsigned long long g2[2][4] = {};
                for (int jb = 0; jb < 8; jb++) {
                    if (jb * 16 <= i0 + 3) {   // chunk-level triangular skip
                        #pragma unroll
                        for (int jj = 0; jj < 16; jj++) {
                            int j = jb * 16 + jj;
                            ulonglong2 ap = *(const ulonglong2*)&a3s[j * 128 + i0];
                            float4 b = *(const float4*)&m3s[j * 64 + cx * 4];
                            unsigned long long bs0 = splat2(b.x), bs1 = splat2(b.y),
                                               bs2 = splat2(b.z), bs3 = splat2(b.w);
                            ffma2(g2[0][0], ap.x, bs0); ffma2(g2[0][1], ap.x, bs1);
                            ffma2(g2[0][2], ap.x, bs2); ffma2(g2[0][3], ap.x, bs3);
                            ffma2(g2[1][0], ap.y, bs0); ffma2(g2[1][1], ap.y, bs1);
                            ffma2(g2[1][2], ap.y, bs2); ffma2(g2[1][3], ap.y, bs3);
                        }
                    }
                }
                // unpack + store to Gpart[i][slot=h][d] (contiguous per-i for R)
                #pragma unroll
                for (int ip = 0; ip < 2; ip++) {
                    float lo[4], hi[4];
                    #pragma unroll
                    for (int c = 0; c < 4; c++) {
                        unsigned int l, hb;
                        asm("mov.b64 {%0, %1}, %2;" : "=r"(l), "=r"(hb) : "l"(g2[ip][c]));
                        lo[c] = __uint_as_float(l);
                        hi[c] = __uint_as_float(hb);
                    }
                    int ia = i0 + 2 * ip, ib2 = i0 + 2 * ip + 1;
                    *(float4*)&Gpart_g[(ia * NSLOT + h) * D + cx * 4] =
                        make_float4(lo[0], lo[1], lo[2], lo[3]);
                    *(float4*)&Gpart_g[(ib2 * NSLOT + h) * D + cx * 4] =
                        make_float4(hi[0], hi[1], hi[2], hi[3]);
                }
            }
        }
        gsync(bar++);

        // ---- phase R (block i): contiguous 32KB partial stream + bias -> G ----
        {
            int i = bid;
            int d = tid & 63, p = tid >> 6;        // 8-way
            float s = 0.0f;
            #pragma unroll
            for (int sl = p; sl < NSLOT; sl += 8)
                s += __ldcg(&Gpart_g[(i * NSLOT + sl) * D + d]);
            #pragma unroll
            for (int r = 0; r < 16; r++) {         // fixed trip; wfun zeroes jj>i
                int jj = p + r * 8;
                s += wfun(i, jj, dt) * __ldcg(&c_g[jj * D + d]);
            }
            part8[p][d] = s;
            __syncthreads();
            if (p == 0) {
                float acc = 0.0f;
                #pragma unroll
                for (int r = 0; r < 8; r++) acc += part8[r][d];
                G_g[i * D + d] = acc;
            }
        }
        gsync(bar++);
    }

    // ---- tail: block 127 computes out = y0 + (w@G)_{127} ----
    if (bid == T - 1) {
        int d = tid & 63, p = tid >> 6;
        float s = 0.0f;
        #pragma unroll
        for (int r = 0; r < 16; r++) {
            int i = p + r * 8;
            s += wfun(T - 1, i, dt) * __ldcg(&G_g[i * D + d]);
        }
        part8[p][d] = s;
        __syncthreads();
        if (p == 0) {
            float acc = z0[d];
            #pragma unroll
            for (int r = 0; r < 8; r++) acc += part8[r][d];
            out[d] = acc;
        }
    }
}

extern "C" void kernel_launch(void* const* d_in, const int* in_sizes, int n_in,
                              void* d_out, int out_size) {
    const float* z0  = (const float*)d_in[0];
    const float* t   = (const float*)d_in[1];
    const float* W1  = (const float*)d_in[2];
    const float* b1  = (const float*)d_in[3];
    const float* W2  = (const float*)d_in[4];
    const float* b2  = (const float*)d_in[5];
    const float* Wk1 = (const float*)d_in[6];
    const float* bk1 = (const float*)d_in[7];
    const float* Wk2 = (const float*)d_in[8];
    const float* bk2 = (const float*)d_in[9];
    float* out = (float*)d_out;

    static int attr_done = 0;
    if (!attr_done) {
        cudaFuncSetAttribute(mega, cudaFuncAttributeMaxDynamicSharedMemorySize, SMEM_BYTES);
        attr_done = 1;
    }
    mega<<<NB, NT, SMEM_BYTES>>>(z0, t, W1, b1, W2, b2, Wk1, bk1, Wk2, bk2, out);
}